// round 1
// baseline (speedup 1.0000x reference)
#include <cuda_runtime.h>
#include <math.h>

#define BB 32
#define PP 64
#define LL 64
#define VV 32000
#define EPSF 1e-13f

// Scratch (no allocations allowed)
__device__ float g_sumAll[BB * PP];
__device__ float g_Ssum[BB * PP];
__device__ int   g_mcount[BB * PP];
__device__ float g_wsum[BB];

// ---------------------------------------------------------------------------
// Kernel B: sumAll[b,i] = sum over V of outputs[b,i,:]  (HBM-bound, 262 MB)
// ---------------------------------------------------------------------------
__global__ void k_sumall(const float* __restrict__ outputs) {
    int bp = blockIdx.x;                       // 0..B*P-1
    const float4* row = (const float4*)(outputs + (size_t)bp * VV);
    float acc = 0.0f;
    #pragma unroll 4
    for (int idx = threadIdx.x; idx < VV / 4; idx += blockDim.x) {
        float4 v = row[idx];
        acc += (v.x + v.y) + (v.z + v.w);
    }
    __shared__ float s[8];
    int lane = threadIdx.x & 31, wid = threadIdx.x >> 5;
    #pragma unroll
    for (int off = 16; off; off >>= 1) acc += __shfl_down_sync(0xffffffffu, acc, off);
    if (lane == 0) s[wid] = acc;
    __syncthreads();
    if (threadIdx.x < 8) {
        acc = s[threadIdx.x];
        #pragma unroll
        for (int off = 4; off; off >>= 1) acc += __shfl_down_sync(0xffu, acc, off);
        if (threadIdx.x == 0) g_sumAll[bp] = acc;
    }
}

// ---------------------------------------------------------------------------
// Kernel A: per-batch edit-distance DP + per-row (min_d, distinct-argmin count m,
// Ssum = sum of outputs at distinct argmin symbols), wsum.
// One block per batch, 64 threads (thread j = column j). All DP values are
// exact small integers in fp32 (all costs == 1.0), so equality vs min is exact.
// ---------------------------------------------------------------------------
__global__ void k_dp(const float* __restrict__ outputs,
                     const int* __restrict__ out_syms,
                     const int* __restrict__ targets,
                     const unsigned char* __restrict__ mask) {
    int b = blockIdx.x;
    int j = threadIdx.x;            // 0..63
    int lane = j & 31, wid = j >> 5;

    __shared__ int   tg[LL];
    __shared__ unsigned char mk[LL];
    __shared__ int   sy[PP];
    __shared__ float prev[LL];
    __shared__ float s_scan[2];
    __shared__ float s_red[2];
    __shared__ float s_red2[2];
    __shared__ unsigned char truth_s[LL];

    tg[j] = targets[b * LL + j];
    mk[j] = mask[b * LL + j];
    sy[j] = out_syms[b * PP + j];
    prev[j] = (float)j;             // row 0
    __syncthreads();

    for (int i = 0; i < PP; i++) {
        float d;
        if (i == 0) {
            d = (float)j;
        } else {
            int sym = sy[i - 1];
            float tmp;
            if (j == 0) {
                tmp = (float)i;
            } else {
                float diag = prev[j - 1] + ((sym != tg[j - 1]) ? 1.0f : 0.0f);
                float ins  = prev[j] + 1.0f;
                tmp = fminf(diag, ins);
            }
            // deletion = min-plus prefix scan: d[j] = j + cummin_{k<=j}(tmp[k]-k)
            float v = tmp - (float)j;
            #pragma unroll
            for (int off = 1; off < 32; off <<= 1) {
                float o = __shfl_up_sync(0xffffffffu, v, off);
                if (lane >= off) v = fminf(v, o);
            }
            if (lane == 31) s_scan[wid] = v;
            __syncthreads();
            if (wid == 1) v = fminf(v, s_scan[0]);
            d = (float)j + v;
            __syncthreads();
            prev[j] = d;
        }

        // ---- row processing ----
        float md = mk[j] ? d : INFINITY;
        float mv = md;
        #pragma unroll
        for (int off = 16; off; off >>= 1) mv = fminf(mv, __shfl_down_sync(0xffffffffu, mv, off));
        if (lane == 0) s_red[wid] = mv;
        __syncthreads();
        float minv = fminf(s_red[0], s_red[1]);
        int istruth = (md == minv);
        truth_s[j] = (unsigned char)istruth;
        __syncthreads();

        float contrib = 0.0f;
        float cm = 0.0f;
        if (istruth) {
            int tv = tg[j];
            bool first = true;
            for (int k = 0; k < j; k++)
                if (truth_s[k] && tg[k] == tv) { first = false; break; }
            if (first) {
                contrib = outputs[(size_t)(b * PP + i) * VV + tv];
                cm = 1.0f;
            }
        }
        #pragma unroll
        for (int off = 16; off; off >>= 1) {
            contrib += __shfl_down_sync(0xffffffffu, contrib, off);
            cm      += __shfl_down_sync(0xffffffffu, cm, off);
        }
        __syncthreads();   // protect s_red (min) reads before sum overwrite
        if (lane == 0) { s_red[wid] = contrib; s_red2[wid] = cm; }
        __syncthreads();
        if (j == 0) {
            g_Ssum[b * PP + i]   = s_red[0] + s_red[1];
            g_mcount[b * PP + i] = (int)(s_red2[0] + s_red2[1]);
        }
        __syncthreads();   // protect shared state for next row
    }

    // wsum
    float w = mk[j] ? 1.0f : 0.0f;
    #pragma unroll
    for (int off = 16; off; off >>= 1) w += __shfl_down_sync(0xffffffffu, w, off);
    if (lane == 0) s_red[wid] = w;
    __syncthreads();
    if (j == 0) g_wsum[b] = s_red[0] + s_red[1];
}

// ---------------------------------------------------------------------------
// Kernel C: analytic KL combine + final reduction (double to guard cancellation)
// kl = m*p1*ln(p1) + (V-m)*p0*ln(p0) - p0*sumAll - (p1-p0)*Ssum
// with p1 = e/(V-m+m*e), p0 = 1/(V-m+m*e)
// loss uses mask[b,i] (P==L broadcast in the reference).
// ---------------------------------------------------------------------------
__global__ void k_final(float* __restrict__ out,
                        const unsigned char* __restrict__ mask) {
    int b = threadIdx.x;  // 0..31
    const double E1 = 2.718281828459045235360287;
    double acc = 0.0;
    for (int i = 0; i < PP; i++) {
        if (!mask[b * LL + i]) continue;
        int bp = b * PP + i;
        double m  = (double)g_mcount[bp];
        double D  = ((double)VV - m) + m * E1;
        double p1 = E1 / D;
        double p0 = 1.0 / D;
        double kl = m * p1 * log(p1) + ((double)VV - m) * p0 * log(p0)
                  - p0 * (double)g_sumAll[bp]
                  - (p1 - p0) * (double)g_Ssum[bp];
        acc += kl;
    }
    double pb = acc / ((double)g_wsum[b] + (double)EPSF);
    double ne = (g_wsum[b] > 0.0f) ? 1.0 : 0.0;
    #pragma unroll
    for (int off = 16; off; off >>= 1) {
        pb += __shfl_down_sync(0xffffffffu, pb, off);
        ne += __shfl_down_sync(0xffffffffu, ne, off);
    }
    if (b == 0) out[0] = (float)(pb / (ne + (double)EPSF));
}

// ---------------------------------------------------------------------------
extern "C" void kernel_launch(void* const* d_in, const int* in_sizes, int n_in,
                              void* d_out, int out_size) {
    const float*         outputs = (const float*)d_in[0];
    const int*           syms    = (const int*)d_in[1];
    const int*           targets = (const int*)d_in[2];
    const unsigned char* mask    = (const unsigned char*)d_in[3];

    k_dp<<<BB, 64>>>(outputs, syms, targets, mask);
    k_sumall<<<BB * PP, 256>>>(outputs);
    k_final<<<1, 32>>>((float*)d_out, mask);
}

// round 2
// speedup vs baseline: 6.8652x; 6.8652x over previous
#include <cuda_runtime.h>
#include <math.h>

#define BB 32
#define PP 64
#define LL 64
#define VV 32000

// Scratch (no allocations allowed)
__device__ uint2  g_mask[BB * PP];     // truth bitmask: .x = even cols, .y = odd cols
__device__ double g_sumAll[BB * PP];
__device__ float  g_Ssum[BB * PP];
__device__ int    g_mcount[BB * PP];

// ---------------------------------------------------------------------------
// Kernel A: warp-per-batch edit-distance DP. Registers + shuffles only.
// Lane t owns columns j0=2t, j1=2t+1. All DP values are exact small integers
// in fp32 (all edit costs == 1.0) so equality-vs-min is bit-exact.
// Emits per (b,i) a 64-bit bitmask of masked argmin columns.
// ---------------------------------------------------------------------------
__global__ void k_dp(const int* __restrict__ syms,
                     const int* __restrict__ targets,
                     const unsigned char* __restrict__ mask) {
    const unsigned FULL = 0xffffffffu;
    int b = blockIdx.x;
    int lane = threadIdx.x;                    // 32 threads
    int j0 = 2 * lane, j1 = 2 * lane + 1;

    int tg0 = targets[b * LL + j0];
    int tg1 = targets[b * LL + j1];
    int mk0 = mask[b * LL + j0];
    int mk1 = mask[b * LL + j1];
    int s0  = syms[b * PP + j0];
    int s1  = syms[b * PP + j1];
    int tgm1 = __shfl_up_sync(FULL, tg1, 1);   // tg[j0-1]

    float p0 = (float)j0, p1 = (float)j1;      // row 0

    for (int i = 0; i < PP; i++) {
        float d0, d1;
        if (i == 0) {
            d0 = p0; d1 = p1;
        } else {
            int im1 = i - 1;
            int sym = __shfl_sync(FULL, (im1 & 1) ? s1 : s0, im1 >> 1);
            float p1m = __shfl_up_sync(FULL, p1, 1);       // prev[j0-1]
            float tmp0 = (lane == 0) ? (float)i
                       : fminf(p1m + ((sym != tgm1) ? 1.0f : 0.0f), p0 + 1.0f);
            float tmp1 = fminf(p0 + ((sym != tg0) ? 1.0f : 0.0f), p1 + 1.0f);
            // deletion prefix-min: d[j] = j + cummin_{k<=j}(tmp[k]-k)
            float v0 = tmp0 - (float)j0;
            float sB = fminf(v0, tmp1 - (float)j1);        // pair-inclusive
            float sc = sB;
            #pragma unroll
            for (int off = 1; off < 32; off <<= 1) {
                float o = __shfl_up_sync(FULL, sc, off);
                if (lane >= off) sc = fminf(sc, o);
            }
            float e = __shfl_up_sync(FULL, sc, 1);         // exclusive prefix
            if (lane == 0) e = INFINITY;
            d0 = (float)j0 + fminf(e, v0);
            d1 = (float)j1 + fminf(e, sB);
            p0 = d0; p1 = d1;
        }
        // masked row min + truth bitmask
        float md0 = mk0 ? d0 : INFINITY;
        float md1 = mk1 ? d1 : INFINITY;
        float mv = fminf(md0, md1);
        #pragma unroll
        for (int off = 16; off; off >>= 1)
            mv = fminf(mv, __shfl_xor_sync(FULL, mv, off));
        unsigned mE = __ballot_sync(FULL, md0 == mv);
        unsigned mO = __ballot_sync(FULL, md1 == mv);
        if (lane == 0) g_mask[b * PP + i] = make_uint2(mE, mO);
    }
}

// ---------------------------------------------------------------------------
// Kernel B (the roofline kernel): one block per (b,i).
//  1) sumAll = sum of outputs row (262 MB streamed, HBM-bound), double acc
//  2) dedup distinct argmin target symbols + gather their outputs (L2-hot)
// ---------------------------------------------------------------------------
__global__ void __launch_bounds__(256) k_main(const float* __restrict__ outputs,
                                              const int* __restrict__ targets) {
    int bp = blockIdx.x;            // 0..2047
    int b  = bp >> 6;
    int lane = threadIdx.x & 31, wid = threadIdx.x >> 5;

    const float4* row4 = (const float4*)(outputs + (size_t)bp * VV);
    double acc = 0.0;
    #pragma unroll 4
    for (int idx = threadIdx.x; idx < VV / 4; idx += 256) {
        float4 v = row4[idx];
        acc += (double)((v.x + v.y) + (v.z + v.w));
    }
    #pragma unroll
    for (int off = 16; off; off >>= 1)
        acc += __shfl_down_sync(0xffffffffu, acc, off);
    __shared__ double sred[8];
    if (lane == 0) sred[wid] = acc;

    __shared__ int stg[LL];
    __shared__ unsigned char str[LL];
    if (threadIdx.x < LL) {
        int j = threadIdx.x;
        stg[j] = targets[b * LL + j];
        uint2 m = g_mask[bp];
        str[j] = (unsigned char)((((j & 1) ? m.y : m.x) >> (j >> 1)) & 1);
    }
    __syncthreads();

    float contrib = 0.0f, cm = 0.0f;
    if (threadIdx.x < LL) {
        int j = threadIdx.x;
        if (str[j]) {
            int tv = stg[j];
            bool first = true;
            for (int k = 0; k < j; k++)
                if (str[k] && stg[k] == tv) { first = false; break; }
            if (first) {
                contrib = outputs[(size_t)bp * VV + tv];   // L2-hot (row just streamed)
                cm = 1.0f;
            }
        }
    }
    #pragma unroll
    for (int off = 16; off; off >>= 1) {
        contrib += __shfl_down_sync(0xffffffffu, contrib, off);
        cm      += __shfl_down_sync(0xffffffffu, cm, off);
    }
    __shared__ float sc2[2], sm2[2];
    if (threadIdx.x < LL && lane == 0) { sc2[wid] = contrib; sm2[wid] = cm; }
    __syncthreads();

    if (threadIdx.x == 0) {
        double s = 0.0;
        #pragma unroll
        for (int w = 0; w < 8; w++) s += sred[w];
        g_sumAll[bp] = s;
        g_Ssum[bp]   = sc2[0] + sc2[1];
        g_mcount[bp] = (int)(sm2[0] + sm2[1]);
    }
}

// ---------------------------------------------------------------------------
// Kernel C: analytic KL combine.
// p1 = e/D, p0 = 1/D, D = (V-m) + m*e ; ln p1 = 1 - ln D ; ln p0 = -ln D
// kl = m*p1*(1-lnD) - (V-m)*p0*lnD - p0*sumAll - (p1-p0)*Ssum
// ---------------------------------------------------------------------------
__global__ void k_final(float* __restrict__ out,
                        const unsigned char* __restrict__ mask) {
    const double E1 = 2.718281828459045235360287;
    __shared__ double skl[BB];
    __shared__ float  sws[BB];
    int t = threadIdx.x;            // 1024
    if (t < BB) { skl[t] = 0.0; sws[t] = 0.0f; }
    __syncthreads();

    for (int bp = t; bp < BB * PP; bp += 1024) {
        int b = bp >> 6, i = bp & 63;
        if (mask[b * LL + i]) {
            double m  = (double)g_mcount[bp];
            double D  = ((double)VV - m) + m * E1;
            double lnD = log(D);
            double p1 = E1 / D;
            double p0 = 1.0 / D;
            double kl = m * p1 * (1.0 - lnD) - ((double)VV - m) * p0 * lnD
                      - p0 * g_sumAll[bp]
                      - (p1 - p0) * (double)g_Ssum[bp];
            atomicAdd(&skl[b], kl);
            atomicAdd(&sws[b], 1.0f);
        }
    }
    __syncthreads();

    if (t < 32) {
        double pb = skl[t] / ((double)sws[t] + 1e-13);
        double ne = (sws[t] > 0.0f) ? 1.0 : 0.0;
        #pragma unroll
        for (int off = 16; off; off >>= 1) {
            pb += __shfl_down_sync(0xffffffffu, pb, off);
            ne += __shfl_down_sync(0xffffffffu, ne, off);
        }
        if (t == 0) out[0] = (float)(pb / (ne + 1e-13));
    }
}

// ---------------------------------------------------------------------------
extern "C" void kernel_launch(void* const* d_in, const int* in_sizes, int n_in,
                              void* d_out, int out_size) {
    const float*         outputs = (const float*)d_in[0];
    const int*           syms    = (const int*)d_in[1];
    const int*           targets = (const int*)d_in[2];
    const unsigned char* mask    = (const unsigned char*)d_in[3];

    k_dp<<<BB, 32>>>(syms, targets, mask);
    k_main<<<BB * PP, 256>>>(outputs, targets);
    k_final<<<1, 1024>>>((float*)d_out, mask);
}

// round 3
// speedup vs baseline: 15.1239x; 2.2030x over previous
#include <cuda_runtime.h>
#include <math.h>

#define BB 32
#define PP 64
#define LL 64
#define VV 32000

// Scratch (no allocations allowed)
__device__ uint2  g_mask[BB * PP];   // truth bitmask per (b,i): .x even cols, .y odd cols
__device__ int    g_flag[BB];        // DP-done flag per batch
__device__ double g_kl[BB];          // per-batch KL accumulator

// ---------------------------------------------------------------------------
// Zero the per-replay accumulators/flags (graph-replay determinism).
// ---------------------------------------------------------------------------
__global__ void k_zero() {
    int t = threadIdx.x;
    if (t < BB) { g_kl[t] = 0.0; g_flag[t] = 0; }
}

// ---------------------------------------------------------------------------
// Fused main kernel: one block per (b,i) row of outputs.
//   blocks 0..31: warp 0 additionally runs the edit-distance DP for batch
//                 (blockIdx.x) first (registers+shuffles), publishes g_mask
//                 + flag, then joins the rowsum.
//   all blocks:   stream-sum their 128KB outputs row (fp32 partials,
//                 double tree-reduce), wait for flag[b], dedup-gather the
//                 distinct argmin target symbols (L2-hot), compute the
//                 analytic KL for this (b,i) in double, atomicAdd per batch.
//
// Analytic collapse of softmax+KL: q has 2 levels -> p1=e/D, p0=1/D with
// D=(V-m)+m*e, m=#distinct argmin symbols. ln p1 = 1-lnD, ln p0 = -lnD.
// kl = m*p1*(1-lnD) - (V-m)*p0*lnD - p0*sumAll - (p1-p0)*Ssum
// ---------------------------------------------------------------------------
__global__ void __launch_bounds__(256) k_main(const float* __restrict__ outputs,
                                              const int* __restrict__ syms,
                                              const int* __restrict__ targets,
                                              const unsigned char* __restrict__ mask) {
    const unsigned FULL = 0xffffffffu;
    int bp   = blockIdx.x;          // 0..2047
    int b    = bp >> 6;
    int i_row = bp & 63;
    int tid  = threadIdx.x;
    int lane = tid & 31, wid = tid >> 5;

    // ---------------- DP (blocks 0..31, warp 0 only) ----------------
    if (bp < BB && wid == 0) {
        int bd = bp;                             // batch handled by this DP warp
        int j0 = 2 * lane, j1 = 2 * lane + 1;
        int tg0 = targets[bd * LL + j0];
        int tg1 = targets[bd * LL + j1];
        int mk0 = mask[bd * LL + j0];
        int mk1 = mask[bd * LL + j1];
        int s0  = syms[bd * PP + j0];
        int s1  = syms[bd * PP + j1];
        int tgm1 = __shfl_up_sync(FULL, tg1, 1); // tg[j0-1]
        float p0 = (float)j0, p1 = (float)j1;    // row 0 (all values exact ints)

        for (int i = 0; i < PP; i++) {
            float d0, d1;
            if (i == 0) {
                d0 = p0; d1 = p1;
            } else {
                int im1 = i - 1;
                int sym = __shfl_sync(FULL, (im1 & 1) ? s1 : s0, im1 >> 1);
                float p1m = __shfl_up_sync(FULL, p1, 1);    // prev[j0-1]
                float tmp0 = (lane == 0) ? (float)i
                           : fminf(p1m + ((sym != tgm1) ? 1.0f : 0.0f), p0 + 1.0f);
                float tmp1 = fminf(p0 + ((sym != tg0) ? 1.0f : 0.0f), p1 + 1.0f);
                float v0 = tmp0 - (float)j0;
                float sB = fminf(v0, tmp1 - (float)j1);     // pair-inclusive
                float sc = sB;
                #pragma unroll
                for (int off = 1; off < 32; off <<= 1) {
                    float o = __shfl_up_sync(FULL, sc, off);
                    if (lane >= off) sc = fminf(sc, o);
                }
                float e = __shfl_up_sync(FULL, sc, 1);      // exclusive prefix
                if (lane == 0) e = INFINITY;
                d0 = (float)j0 + fminf(e, v0);
                d1 = (float)j1 + fminf(e, sB);
                p0 = d0; p1 = d1;
            }
            float md0 = mk0 ? d0 : INFINITY;
            float md1 = mk1 ? d1 : INFINITY;
            float mv = fminf(md0, md1);
            #pragma unroll
            for (int off = 16; off; off >>= 1)
                mv = fminf(mv, __shfl_xor_sync(FULL, mv, off));
            unsigned mE = __ballot_sync(FULL, md0 == mv);
            unsigned mO = __ballot_sync(FULL, md1 == mv);
            if (lane == 0) g_mask[bd * PP + i] = make_uint2(mE, mO);
        }
        __threadfence();
        if (lane == 0) atomicExch(&g_flag[bd], 1);
    }

    // ---------------- rowsum (all blocks, HBM-bound) ----------------
    const float4* row4 = (const float4*)(outputs + (size_t)bp * VV);
    float acc = 0.0f;
    #pragma unroll 4
    for (int idx = tid; idx < VV / 4; idx += 256) {
        float4 v = row4[idx];
        acc += (v.x + v.y) + (v.z + v.w);
    }
    double dacc = (double)acc;
    #pragma unroll
    for (int off = 16; off; off >>= 1)
        dacc += __shfl_down_sync(FULL, dacc, off);
    __shared__ double sred[8];
    if (lane == 0) sred[wid] = dacc;

    // ---------------- wait for this batch's DP mask ----------------
    if (tid == 0) {
        while (atomicAdd(&g_flag[b], 0) == 0) __nanosleep(64);
    }
    __syncthreads();
    __threadfence();

    // ---------------- dedup gather of distinct argmin symbols ------
    __shared__ int stg[LL];
    __shared__ unsigned char str[LL];
    if (tid < LL) {
        stg[tid] = targets[b * LL + tid];
        uint2 m = g_mask[bp];
        str[tid] = (unsigned char)((((tid & 1) ? m.y : m.x) >> (tid >> 1)) & 1);
    }
    __syncthreads();

    float contrib = 0.0f, cm = 0.0f;
    if (tid < LL && str[tid]) {
        int tv = stg[tid];
        bool first = true;
        for (int k = 0; k < tid; k++)
            if (str[k] && stg[k] == tv) { first = false; break; }
        if (first) {
            contrib = outputs[(size_t)bp * VV + tv];   // L2-hot: row just streamed
            cm = 1.0f;
        }
    }
    #pragma unroll
    for (int off = 16; off; off >>= 1) {
        contrib += __shfl_down_sync(FULL, contrib, off);
        cm      += __shfl_down_sync(FULL, cm, off);
    }
    __shared__ float sc2[2], sm2[2];
    if (tid < LL && lane == 0) { sc2[wid] = contrib; sm2[wid] = cm; }
    __syncthreads();

    // ---------------- per-(b,i) KL (double) -------------------------
    if (tid == 0 && mask[b * LL + i_row]) {
        double sumAll = 0.0;
        #pragma unroll
        for (int w = 0; w < 8; w++) sumAll += sred[w];
        double Ssum = (double)(sc2[0] + sc2[1]);
        double m    = (double)(sm2[0] + sm2[1]);
        const double E1 = 2.718281828459045235360287;
        double D   = ((double)VV - m) + m * E1;
        double lnD = log(D);
        double p1  = E1 / D;
        double pz  = 1.0 / D;
        double kl  = m * p1 * (1.0 - lnD) - ((double)VV - m) * pz * lnD
                   - pz * sumAll - (p1 - pz) * Ssum;
        atomicAdd(&g_kl[b], kl);
    }
}

// ---------------------------------------------------------------------------
// Finisher: per-batch normalize + mean over nonempty batches.
// ---------------------------------------------------------------------------
__global__ void k_final(float* __restrict__ out,
                        const unsigned char* __restrict__ mask) {
    int b = threadIdx.x;  // 0..31
    float w = 0.0f;
    #pragma unroll
    for (int j = 0; j < LL; j++) w += (float)mask[b * LL + j];
    double pb = g_kl[b] / ((double)w + 1e-13);
    double ne = (w > 0.0f) ? 1.0 : 0.0;
    #pragma unroll
    for (int off = 16; off; off >>= 1) {
        pb += __shfl_down_sync(0xffffffffu, pb, off);
        ne += __shfl_down_sync(0xffffffffu, ne, off);
    }
    if (b == 0) out[0] = (float)(pb / (ne + 1e-13));
}

// ---------------------------------------------------------------------------
extern "C" void kernel_launch(void* const* d_in, const int* in_sizes, int n_in,
                              void* d_out, int out_size) {
    const float*         outputs = (const float*)d_in[0];
    const int*           syms    = (const int*)d_in[1];
    const int*           targets = (const int*)d_in[2];
    const unsigned char* mask    = (const unsigned char*)d_in[3];

    k_zero<<<1, 32>>>();
    k_main<<<BB * PP, 256>>>(outputs, syms, targets, mask);
    k_final<<<1, 32>>>((float*)d_out, mask);
}